// round 16
// baseline (speedup 1.0000x reference)
#include <cuda_runtime.h>
#include <cuda_fp16.h>

#define NB 32
#define NC 2
#define NL 262144
#define NT 1024
#define NF 257
#define AMINF 1e-10f
#define TEN_OVER_LOG2_10 3.0102999566398120f

#define MFR 65536   // total frames
#define KD  512     // GEMM K
#define KC  64      // K chunk (fp16 elements)
#define BM  256     // CTA m tile
#define BN  128     // CTA n tile

// smem: A tile 256x144B + B tile 128x144B, double buffered
#define ROWB   144
#define T_A    0
#define T_B    (BM * ROWB)               // 36864
#define BUFB   (T_B + BN * ROWB)         // 55296
#define SMEM_TOTAL (2 * BUFB)            // 110592 -> 2 CTAs/SM

// ---- scratch ----
__device__ unsigned short g_Ah[(size_t)MFR * KD];    // 64 MB, fp16 frames
__device__ unsigned short g_B[512 * KD];             // rows: 2f=re_f, 2f+1=im_f; row1 = re_256
__device__ float g_P[(size_t)64 * NF * NT];          // log-power scratch [bc][f][t]
__device__ unsigned int g_pmax;

// ---- helpers ----
__device__ __forceinline__ unsigned smem_u32(const void* p) {
    unsigned a;
    asm("{ .reg .u64 t; cvta.to.shared.u64 t, %1; cvt.u32.u64 %0, t; }"
        : "=r"(a) : "l"(p));
    return a;
}
#define CP16(dst, src) \
    asm volatile("cp.async.cg.shared.global [%0], [%1], 16;" :: "r"(dst), "l"(src))
#define CPCOMMIT() asm volatile("cp.async.commit_group;" ::: "memory")
#define CPWAIT(n)  asm volatile("cp.async.wait_group %0;" :: "n"(n) : "memory")

__device__ __forceinline__ void ldsm4(unsigned* r, unsigned addr) {
    asm volatile("ldmatrix.sync.aligned.m8n8.x4.shared.b16 {%0,%1,%2,%3}, [%4];"
                 : "=r"(r[0]), "=r"(r[1]), "=r"(r[2]), "=r"(r[3]) : "r"(addr));
}
__device__ __forceinline__ void mma_fp16(float* d, const unsigned* a,
                                         const unsigned* b) {
    asm volatile(
        "mma.sync.aligned.m16n8k16.row.col.f32.f16.f16.f32 "
        "{%0,%1,%2,%3}, {%4,%5,%6,%7}, {%8,%9}, {%0,%1,%2,%3};"
        : "+f"(d[0]), "+f"(d[1]), "+f"(d[2]), "+f"(d[3])
        : "r"(a[0]), "r"(a[1]), "r"(a[2]), "r"(a[3]), "r"(b[0]), "r"(b[1]));
}

// ---------------------------------------------------------------------------
// prep_B: fp16 B. Row n=2f -> k_real bin f, n=2f+1 -> k_imag bin f,
// EXCEPT row 1 (im_0 == 0) carries re of the Nyquist bin f=256.
// ---------------------------------------------------------------------------
__global__ void prep_B(const float* __restrict__ kre,
                       const float* __restrict__ kim) {
    int i = blockIdx.x * 256 + threadIdx.x;  // 0..262143
    int n = i >> 9, k = i & 511;
    int f = n >> 1;
    float v;
    if (n == 1)       v = kre[(size_t)k * NF + 256];
    else if (n & 1)   v = kim[(size_t)k * NF + f];
    else              v = kre[(size_t)k * NF + f];
    g_B[(size_t)n * KD + k] = __half_as_ushort(__float2half_rn(v));
    if (i == 0) g_pmax = 0u;
}

// ---------------------------------------------------------------------------
// prep_A: frame extraction -> fp16 scratch [MFR x 512].
// ---------------------------------------------------------------------------
__global__ void prep_A(const float* __restrict__ x) {
    int idx = blockIdx.x * 256 + threadIdx.x;
    int m = idx >> 6;
    int d0 = (idx & 63) << 3;
    int t = m & (NT - 1);
    int bc = m >> 10;
    const float* xp = x + (size_t)bc * NL;
    int g0 = t * 256 + d0 - 128;
    float v[8];
    if (g0 >= 0 && g0 + 8 <= NL) {
        float4 u0 = *(const float4*)(xp + g0);
        float4 u1 = *(const float4*)(xp + g0 + 4);
        v[0] = u0.x; v[1] = u0.y; v[2] = u0.z; v[3] = u0.w;
        v[4] = u1.x; v[5] = u1.y; v[6] = u1.z; v[7] = u1.w;
    } else {
#pragma unroll
        for (int j = 0; j < 8; j++) {
            int g = g0 + j;
            v[j] = (g >= 0 && g < NL) ? xp[g] : 0.f;
        }
    }
    unsigned hw[4];
#pragma unroll
    for (int j = 0; j < 4; j++) {
        __half h0 = __float2half_rn(v[2 * j]);
        __half h1 = __float2half_rn(v[2 * j + 1]);
        hw[j] = (unsigned)__half_as_ushort(h0) |
                ((unsigned)__half_as_ushort(h1) << 16);
    }
    *(uint4*)(g_Ah + (size_t)m * KD + d0) = make_uint4(hw[0], hw[1], hw[2], hw[3]);
}

// ---------------------------------------------------------------------------
// spec_gemm: CTA tile 256(m) x 128(n), K=512 in 8 chunks, cp.async double buf.
// 8 warps 4(m)x2(n), warp tile 64x64. grid = (4 ntiles, 256 mtiles).
// 110.6 KB smem -> 2 CTAs/SM.
// ---------------------------------------------------------------------------
__global__ __launch_bounds__(256) void spec_gemm(float* __restrict__ P) {
    extern __shared__ char smem[];
    const unsigned sb = smem_u32(smem);
    const int tid = threadIdx.x;
    const int wid = tid >> 5, lane = tid & 31;
    const int warp_m = wid >> 1, warp_n = wid & 1;
    const int m0 = blockIdx.y * BM, n0 = blockIdx.x * BN;

    float d[4][8][4];
#pragma unroll
    for (int mi = 0; mi < 4; mi++)
#pragma unroll
        for (int ni = 0; ni < 8; ni++)
#pragma unroll
            for (int r = 0; r < 4; r++) d[mi][ni][r] = 0.f;

    const unsigned a_base = (unsigned)((warp_m * 64 + (lane & 15)) * ROWB +
                                       ((lane >> 4) << 4));
    // x4 B: lanes 0-7 rows+0..7/seg0, 8-15 rows+0..7/seg1,
    //       16-23 rows+8..15/seg0, 24-31 rows+8..15/seg1
    const unsigned b_base = (unsigned)((warp_n * 64 + (lane & 7) +
                                        ((lane >> 4) << 3)) * ROWB +
                                       (((lane >> 3) & 1) << 4));

    auto stage = [&](int buf, int ch) {
        const int k0 = ch * KC;
        const unsigned base = sb + buf * BUFB;
        // A: 256 rows x 8 segs = 2048 cp
#pragma unroll
        for (int rep = 0; rep < 8; rep++) {
            int i = rep * 256 + tid;
            int row = i >> 3, seg = i & 7;
            const unsigned short* src = g_Ah + ((size_t)(m0 + row) * KD + k0);
            CP16(base + T_A + row * ROWB + seg * 16, src + seg * 8);
        }
        // B: 128 rows x 8 segs = 1024 cp
#pragma unroll
        for (int rep = 0; rep < 4; rep++) {
            int i = rep * 256 + tid;
            int row = i >> 3, seg = i & 7;
            const unsigned short* src = g_B + ((size_t)(n0 + row) * KD + k0);
            CP16(base + T_B + row * ROWB + seg * 16, src + seg * 8);
        }
        CPCOMMIT();
    };

    stage(0, 0);
    for (int ch = 0; ch < 8; ch++) {
        const int buf = ch & 1;
        if (ch < 7) { stage(buf ^ 1, ch + 1); CPWAIT(1); }
        else        { CPWAIT(0); }
        __syncthreads();

        const unsigned abase = sb + buf * BUFB + T_A + a_base;
        const unsigned bbase = sb + buf * BUFB + T_B + b_base;
#pragma unroll
        for (int ks = 0; ks < 4; ks++) {
            unsigned a[4][4], bf[8][2];
#pragma unroll
            for (int mi = 0; mi < 4; mi++)
                ldsm4(a[mi], abase + mi * (16 * ROWB) + ks * 32);
#pragma unroll
            for (int nh = 0; nh < 4; nh++) {
                unsigned r[4];
                ldsm4(r, bbase + nh * (16 * ROWB) + ks * 32);
                bf[2 * nh][0] = r[0]; bf[2 * nh][1] = r[1];
                bf[2 * nh + 1][0] = r[2]; bf[2 * nh + 1][1] = r[3];
            }
#pragma unroll
            for (int mi = 0; mi < 4; mi++)
#pragma unroll
                for (int ni = 0; ni < 8; ni++)
                    mma_fp16(d[mi][ni], a[mi], bf[ni]);
        }
        __syncthreads();
    }

    // ---- epilogue: col pairs (re_f, im_f); f==0 pair is (re_0, re_256) ----
    float pmax = 0.f;
    const int fbase = (n0 >> 1) + warp_n * 32 + (lane & 3);
#pragma unroll
    for (int mi = 0; mi < 4; mi++) {
        int mrow = m0 + warp_m * 64 + mi * 16 + (lane >> 2);
#pragma unroll
        for (int h = 0; h < 2; h++) {
            int m = mrow + h * 8;
            int bc = m >> 10, t = m & (NT - 1);
#pragma unroll
            for (int ni = 0; ni < 8; ni++) {
                float re = d[mi][ni][2 * h];
                float im = d[mi][ni][2 * h + 1];
                int f = fbase + ni * 4;
                if (f == 0) {
                    // im slot carries re of Nyquist bin; true im_0 == 0
                    float p0 = fmaxf(re * re, AMINF);
                    float pn = fmaxf(im * im, AMINF);
                    pmax = fmaxf(pmax, fmaxf(p0, pn));
                    g_P[((size_t)bc * NF + 0) * NT + t] =
                        TEN_OVER_LOG2_10 * __log2f(p0);
                    g_P[((size_t)bc * NF + 256) * NT + t] =
                        TEN_OVER_LOG2_10 * __log2f(pn);
                } else {
                    float p = fmaxf(fmaf(re, re, im * im), AMINF);
                    pmax = fmaxf(pmax, p);
                    g_P[((size_t)bc * NF + f) * NT + t] =
                        TEN_OVER_LOG2_10 * __log2f(p);
                }
            }
        }
    }
#pragma unroll
    for (int o = 16; o; o >>= 1)
        pmax = fmaxf(pmax, __shfl_xor_sync(0xFFFFFFFFu, pmax, o));
    __shared__ float red[8];
    if (lane == 0) red[wid] = pmax;
    __syncthreads();
    if (tid == 0) {
        float mm = red[0];
#pragma unroll
        for (int w = 1; w < 8; w++) mm = fmaxf(mm, red[w]);
        atomicMax(&g_pmax, __float_as_uint(mm));
    }
}

// ---------------------------------------------------------------------------
// spec_fin: transpose-interleave g_P[bc][f][t] -> out[b][f][t][c], subtract
// global max, clamp. One block per (b,f) row; coalesced both sides.
// ---------------------------------------------------------------------------
__global__ void spec_fin(float* __restrict__ out) {
    const int bf = blockIdx.x;          // 0..32*257-1
    const int b = bf / NF, f = bf % NF;
    const float lmax =
        TEN_OVER_LOG2_10 * __log2f(fmaxf(__uint_as_float(g_pmax), AMINF));
    const float* s0 = g_P + ((size_t)(b * 2 + 0) * NF + f) * NT;
    const float* s1 = g_P + ((size_t)(b * 2 + 1) * NF + f) * NT;
    float2* orow = (float2*)(out + ((size_t)b * NF + f) * NT * NC);
#pragma unroll
    for (int j = 0; j < 4; j++) {
        int t = j * 256 + threadIdx.x;
        float2 v;
        v.x = fmaxf(s0[t] - lmax, -80.f);
        v.y = fmaxf(s1[t] - lmax, -80.f);
        orow[t] = v;
    }
}

extern "C" void kernel_launch(void* const* d_in, const int* in_sizes, int n_in,
                              void* d_out, int out_size) {
    const float* x = (const float*)d_in[0];
    const float* kre = (const float*)d_in[1];
    const float* kim = (const float*)d_in[2];
    float* out = (float*)d_out;

    cudaFuncSetAttribute(spec_gemm, cudaFuncAttributeMaxDynamicSharedMemorySize,
                         SMEM_TOTAL);

    prep_B<<<1024, 256>>>(kre, kim);
    prep_A<<<16384, 256>>>(x);

    float* P;
    cudaGetSymbolAddress((void**)&P, g_P);
    spec_gemm<<<dim3(4, MFR / BM), 256, SMEM_TOTAL>>>(P);
    spec_fin<<<NB * NF, 256>>>(out);
}

// round 17
// speedup vs baseline: 1.1466x; 1.1466x over previous
#include <cuda_runtime.h>
#include <cuda_fp16.h>

#define NB 32
#define NC 2
#define NL 262144
#define NT 1024
#define NF 257
#define AMINF 1e-10f
#define L10 3.0102999566398120f   // 10/log2(10)

#define MFR 65536   // total frames
#define KF  256     // folded GEMM K
#define KC  32      // K chunk
#define NCH 8

// smem: A_s,A_a 128 rows + B_re,B_im 64 rows; 80B row stride; double buffered
#define ROWB  80
#define T_AS  0
#define T_AA  (128 * ROWB)            // 10240
#define T_BRE (2 * 128 * ROWB)        // 20480
#define T_BIM (T_BRE + 64 * ROWB)     // 25600
#define BUFB  (T_BIM + 64 * ROWB)     // 30720
#define SMEM_TOTAL (2 * BUFB)         // 61440 -> 2 CTAs/SM

// ---- scratch ----
__device__ unsigned short g_A[(size_t)MFR * 512];  // cols 0..255 = s, 256..511 = a (fp16)
__device__ unsigned short g_B[512 * KF];           // rows 0..255 re-kernels, 256..511 im-kernels
__device__ float g_kn[256];                        // folded Nyquist coeffs
__device__ float g_P[(size_t)64 * NF * NT];        // log-power scratch [bc][f][t]
__device__ unsigned int g_pmax;

// ---- helpers ----
__device__ __forceinline__ unsigned smem_u32(const void* p) {
    unsigned a;
    asm("{ .reg .u64 t; cvta.to.shared.u64 t, %1; cvt.u32.u64 %0, t; }"
        : "=r"(a) : "l"(p));
    return a;
}
#define CP16(dst, src) \
    asm volatile("cp.async.cg.shared.global [%0], [%1], 16;" :: "r"(dst), "l"(src))
#define CPCOMMIT() asm volatile("cp.async.commit_group;" ::: "memory")
#define CPWAIT(n)  asm volatile("cp.async.wait_group %0;" :: "n"(n) : "memory")

__device__ __forceinline__ void ldsm4(unsigned* r, unsigned addr) {
    asm volatile("ldmatrix.sync.aligned.m8n8.x4.shared.b16 {%0,%1,%2,%3}, [%4];"
                 : "=r"(r[0]), "=r"(r[1]), "=r"(r[2]), "=r"(r[3]) : "r"(addr));
}
__device__ __forceinline__ void mma_fp16(float* d, const unsigned* a,
                                         const unsigned* b) {
    asm volatile(
        "mma.sync.aligned.m16n8k16.row.col.f32.f16.f16.f32 "
        "{%0,%1,%2,%3}, {%4,%5,%6,%7}, {%8,%9}, {%0,%1,%2,%3};"
        : "+f"(d[0]), "+f"(d[1]), "+f"(d[2]), "+f"(d[3])
        : "r"(a[0]), "r"(a[1]), "r"(a[2]), "r"(a[3]), "r"(b[0]), "r"(b[1]));
}

// ---------------------------------------------------------------------------
// prep_B: folded B (fp16) + Nyquist coeff vector + pmax reset.
// Row n<256: re-kernel bin f=n over s: k=0 -> kre[256][n], k>=1 -> kre[k][n].
// Row n>=256: im-kernel bin f=n-256 over a: kim[k][f] (k=0 slot -> 0).
// grid = 512 x 256.
// ---------------------------------------------------------------------------
__global__ void prep_B(const float* __restrict__ kre,
                       const float* __restrict__ kim) {
    int i = blockIdx.x * 256 + threadIdx.x;  // 0..131071
    int n = i >> 8, k = i & 255;
    float v;
    if (n < 256) {
        v = (k == 0) ? kre[(size_t)256 * NF + n] : kre[(size_t)k * NF + n];
    } else {
        int f = n - 256;
        v = (k == 0 || f == 0) ? 0.f : kim[(size_t)k * NF + f];
    }
    g_B[(size_t)n * KF + k] = __half_as_ushort(__float2half_rn(v));
    if (blockIdx.x == 0) {
        int s = threadIdx.x;  // 0..255
        g_kn[s] = (s == 0) ? kre[(size_t)256 * NF + 256]
                           : kre[(size_t)s * NF + 256];
    }
    if (i == 0) g_pmax = 0u;
}

// ---------------------------------------------------------------------------
// prep_A: fold frames -> fp16 [s|a] scratch; compute Nyquist bin per frame.
// 1 warp = 1 frame; block = 8 frames. grid = 8192 x 256.
// ---------------------------------------------------------------------------
__device__ __forceinline__ void load8g(float* v, const float* xp, int g) {
    if (g >= 0 && g + 7 < NL) {
        float4 u0 = *(const float4*)(xp + g);
        float4 u1 = *(const float4*)(xp + g + 4);
        v[0] = u0.x; v[1] = u0.y; v[2] = u0.z; v[3] = u0.w;
        v[4] = u1.x; v[5] = u1.y; v[6] = u1.z; v[7] = u1.w;
    } else {
#pragma unroll
        for (int j = 0; j < 8; j++) {
            int gg = g + j;
            v[j] = (gg >= 0 && gg < NL) ? xp[gg] : 0.f;
        }
    }
}

__global__ void prep_A(const float* __restrict__ x) {
    const int wid = threadIdx.x >> 5, lane = threadIdx.x & 31;
    const int m = blockIdx.x * 8 + wid;
    const int t = m & (NT - 1), bc = m >> 10;
    const float* xp = x + (size_t)bc * NL;
    const int g0 = t * 256 - 128;

    float F[8], Bv[8];
    load8g(F, xp, g0 + 8 * lane);          // x[g0+8l .. +7]   (d = 8l..8l+7)
    load8g(Bv, xp, g0 + 504 - 8 * lane);   // x[g0+504-8l..+7] (mirrors d=8l+1..8l+8)
    float mir0 = __shfl_up_sync(0xFFFFFFFFu, Bv[0], 1);  // x[g0+512-8l]

    float kn[8];
    *(float4*)kn       = *(const float4*)&g_kn[8 * lane];
    *(float4*)(kn + 4) = *(const float4*)&g_kn[8 * lane + 4];

    float s[8], a[8], nyq = 0.f;
#pragma unroll
    for (int jj = 0; jj < 8; jj++) {
        if (jj == 0 && lane == 0) {
            s[0] = xp[g0 + 256];   // always in [128, 262016]
            a[0] = 0.f;
        } else {
            float bwv = (jj == 0) ? mir0 : Bv[8 - jj];
            s[jj] = F[jj] + bwv;
            a[jj] = F[jj] - bwv;
        }
        nyq = fmaf(s[jj], kn[jj], nyq);
    }

    unsigned hs[4], ha[4];
#pragma unroll
    for (int j = 0; j < 4; j++) {
        hs[j] = (unsigned)__half_as_ushort(__float2half_rn(s[2 * j])) |
                ((unsigned)__half_as_ushort(__float2half_rn(s[2 * j + 1])) << 16);
        ha[j] = (unsigned)__half_as_ushort(__float2half_rn(a[2 * j])) |
                ((unsigned)__half_as_ushort(__float2half_rn(a[2 * j + 1])) << 16);
    }
    *(uint4*)&g_A[(size_t)m * 512 + 8 * lane] = make_uint4(hs[0], hs[1], hs[2], hs[3]);
    *(uint4*)&g_A[(size_t)m * 512 + 256 + 8 * lane] = make_uint4(ha[0], ha[1], ha[2], ha[3]);

    // Nyquist: warp reduce, write bin f=256
#pragma unroll
    for (int o = 16; o; o >>= 1) nyq += __shfl_xor_sync(0xFFFFFFFFu, nyq, o);
    __shared__ float red[8];
    if (lane == 0) {
        float p = fmaxf(nyq * nyq, AMINF);
        g_P[((size_t)bc * NF + 256) * NT + t] = L10 * __log2f(p);
        red[wid] = p;
    }
    __syncthreads();
    if (threadIdx.x == 0) {
        float mm = red[0];
#pragma unroll
        for (int w = 1; w < 8; w++) mm = fmaxf(mm, red[w]);
        atomicMax(&g_pmax, __float_as_uint(mm));
    }
}

// ---------------------------------------------------------------------------
// spec_gemm: folded. CTA = 128 m x 64 f (re+im both), K=256 in 8 chunks of 32.
// 8 warps 2(m)x4(f); warp = 64m x 16f, computes d_re = A_s*B_re and
// d_im = A_a*B_im locally -> power fused in epilogue.
// grid = (4 ftiles, 512 mtiles); 60 KB smem, 2 CTAs/SM.
// ---------------------------------------------------------------------------
__global__ __launch_bounds__(256, 2) void spec_gemm(float* __restrict__ P) {
    extern __shared__ char smem[];
    const unsigned sb = smem_u32(smem);
    const int tid = threadIdx.x;
    const int wid = tid >> 5, lane = tid & 31;
    const int warp_m = wid >> 2, warp_n = wid & 3;
    const int m0 = blockIdx.y * 128, f0 = blockIdx.x * 64;

    float dre[4][2][4], dim[4][2][4];
#pragma unroll
    for (int mi = 0; mi < 4; mi++)
#pragma unroll
        for (int nb = 0; nb < 2; nb++)
#pragma unroll
            for (int r = 0; r < 4; r++) { dre[mi][nb][r] = 0.f; dim[mi][nb][r] = 0.f; }

    const unsigned a_off = (unsigned)((warp_m * 64 + (lane & 15)) * ROWB +
                                      ((lane >> 4) << 4));
    const unsigned b_off = (unsigned)((warp_n * 16 + (lane & 7) +
                                       ((lane >> 4) << 3)) * ROWB +
                                      (((lane >> 3) & 1) << 4));

    auto stage = [&](int buf, int ch) {
        const int k0 = ch * KC;  // halves
        const unsigned base = sb + buf * BUFB;
#pragma unroll
        for (int rep = 0; rep < 6; rep++) {
            int i = rep * 256 + tid;  // 0..1535
            int seg = i & 3;
            unsigned dst;
            const unsigned short* src;
            if (i < 512) {           // A_s: 128 rows
                int row = i >> 2;
                src = g_A + ((size_t)(m0 + row) * 512 + k0 + seg * 8);
                dst = base + T_AS + row * ROWB + seg * 16;
            } else if (i < 1024) {   // A_a
                int row = (i - 512) >> 2;
                src = g_A + ((size_t)(m0 + row) * 512 + 256 + k0 + seg * 8);
                dst = base + T_AA + row * ROWB + seg * 16;
            } else if (i < 1280) {   // B_re: 64 rows
                int row = (i - 1024) >> 2;
                src = g_B + ((size_t)(f0 + row) * KF + k0 + seg * 8);
                dst = base + T_BRE + row * ROWB + seg * 16;
            } else {                 // B_im
                int row = (i - 1280) >> 2;
                src = g_B + ((size_t)(256 + f0 + row) * KF + k0 + seg * 8);
                dst = base + T_BIM + row * ROWB + seg * 16;
            }
            CP16(dst, src);
        }
        CPCOMMIT();
    };

    stage(0, 0);
    for (int ch = 0; ch < NCH; ch++) {
        const int buf = ch & 1;
        if (ch < NCH - 1) { stage(buf ^ 1, ch + 1); CPWAIT(1); }
        else              { CPWAIT(0); }
        __syncthreads();

        const unsigned bs = sb + buf * BUFB;
#pragma unroll
        for (int ks = 0; ks < 2; ks++) {
            unsigned as[4][4], aa[4][4], bre[2][2], bim[2][2];
#pragma unroll
            for (int mi = 0; mi < 4; mi++) {
                ldsm4(as[mi], bs + T_AS + a_off + mi * (16 * ROWB) + ks * 32);
                ldsm4(aa[mi], bs + T_AA + a_off + mi * (16 * ROWB) + ks * 32);
            }
            {
                unsigned r[4];
                ldsm4(r, bs + T_BRE + b_off + ks * 32);
                bre[0][0] = r[0]; bre[0][1] = r[1];
                bre[1][0] = r[2]; bre[1][1] = r[3];
                ldsm4(r, bs + T_BIM + b_off + ks * 32);
                bim[0][0] = r[0]; bim[0][1] = r[1];
                bim[1][0] = r[2]; bim[1][1] = r[3];
            }
#pragma unroll
            for (int mi = 0; mi < 4; mi++)
#pragma unroll
                for (int nb = 0; nb < 2; nb++) {
                    mma_fp16(dre[mi][nb], as[mi], bre[nb]);
                    mma_fp16(dim[mi][nb], aa[mi], bim[nb]);
                }
        }
        __syncthreads();
    }

    // ---- epilogue: p = re^2 + im^2 locally (im_0 column is all-zero) ----
    float pmax = 0.f;
#pragma unroll
    for (int mi = 0; mi < 4; mi++)
#pragma unroll
        for (int nb = 0; nb < 2; nb++)
#pragma unroll
            for (int r = 0; r < 4; r++) {
                int row = warp_m * 64 + mi * 16 + (lane >> 2) + ((r >> 1) << 3);
                int m = m0 + row;
                int bc = m >> 10, t = m & (NT - 1);
                int f = f0 + warp_n * 16 + nb * 8 + ((lane & 3) << 1) + (r & 1);
                float re = dre[mi][nb][r], im = dim[mi][nb][r];
                float p = fmaxf(fmaf(re, re, im * im), AMINF);
                pmax = fmaxf(pmax, p);
                P[((size_t)bc * NF + f) * NT + t] = L10 * __log2f(p);
            }
#pragma unroll
    for (int o = 16; o; o >>= 1)
        pmax = fmaxf(pmax, __shfl_xor_sync(0xFFFFFFFFu, pmax, o));
    __shared__ float red[8];
    if (lane == 0) red[wid] = pmax;
    __syncthreads();
    if (tid == 0) {
        float mm = red[0];
#pragma unroll
        for (int w = 1; w < 8; w++) mm = fmaxf(mm, red[w]);
        atomicMax(&g_pmax, __float_as_uint(mm));
    }
}

// ---------------------------------------------------------------------------
// spec_fin: transpose-interleave g_P[bc][f][t] -> out[b][f][t][c], subtract
// global max (log domain), clamp. One block per (b,f) row.
// ---------------------------------------------------------------------------
__global__ void spec_fin(float* __restrict__ out) {
    const int bf = blockIdx.x;          // 0..32*257-1
    const int b = bf / NF, f = bf % NF;
    const float lmax =
        L10 * __log2f(fmaxf(__uint_as_float(g_pmax), AMINF));
    const float* s0 = g_P + ((size_t)(b * 2 + 0) * NF + f) * NT;
    const float* s1 = g_P + ((size_t)(b * 2 + 1) * NF + f) * NT;
    float2* orow = (float2*)(out + ((size_t)b * NF + f) * NT * NC);
#pragma unroll
    for (int j = 0; j < 4; j++) {
        int t = j * 256 + threadIdx.x;
        float2 v;
        v.x = fmaxf(s0[t] - lmax, -80.f);
        v.y = fmaxf(s1[t] - lmax, -80.f);
        orow[t] = v;
    }
}

extern "C" void kernel_launch(void* const* d_in, const int* in_sizes, int n_in,
                              void* d_out, int out_size) {
    const float* x = (const float*)d_in[0];
    const float* kre = (const float*)d_in[1];
    const float* kim = (const float*)d_in[2];
    float* out = (float*)d_out;

    cudaFuncSetAttribute(spec_gemm, cudaFuncAttributeMaxDynamicSharedMemorySize,
                         SMEM_TOTAL);

    prep_B<<<512, 256>>>(kre, kim);
    prep_A<<<MFR / 8, 256>>>(x);

    float* P;
    cudaGetSymbolAddress((void**)&P, g_P);
    spec_gemm<<<dim3(4, MFR / 128), 256, SMEM_TOTAL>>>(P);
    spec_fin<<<NB * NF, 256>>>(out);
}